// round 1
// baseline (speedup 1.0000x reference)
#include <cuda_runtime.h>
#include <math.h>

// Problem dims (fixed by the dataset)
#define S_IN   128
#define V_IN   16
#define HID    16
#define SVO    3
#define S_OUT  128
#define V_OUT  16
#define MAXN   50000
#define EPS    1e-8f

// -------- scratch (device globals; no allocation allowed) --------
__device__ float g_fsum[MAXN * 9];   // per-node sum of 3x3 frames over out-edges
__device__ float g_cnt [MAXN];       // per-node edge count

// -------- shared memory layout for node kernel (floats) ----------
#define OFF_WSO    0            // W_so transposed [k*129 + o], k<153, o<128 (stride 129 -> conflict free)
#define SZ_WSO     19740        // 153*129 = 19737, padded to /4
#define OFF_WG     (OFF_WSO + SZ_WSO)       // W_g transposed [k*17 + o], k<128, o<16
#define SZ_WG      2176                      // 128*17
#define OFF_WUP    (OFF_WG + SZ_WG)          // W_up transposed [h*16 + o]
#define SZ_WUP     256
#define OFF_WDOWN  (OFF_WUP + SZ_WUP)        // W_down transposed [c*16 + h]
#define SZ_WDOWN   256
#define OFF_WDF    (OFF_WDOWN + SZ_WDOWN)    // W_df transposed [k*3 + c]
#define SZ_WDF     48
#define OFF_BSO    (OFF_WDF + SZ_WDF)
#define SZ_BSO     128
#define OFF_BG     (OFF_BSO + SZ_BSO)
#define SZ_BG      16
#define OFF_WARP   (OFF_BG + SZ_BG)          // per-warp: merged[160] + vec[48] + vh[48] = 256
#define WARP_STRIDE 256
#define NWARPS     8
#define SMEM_FLOATS (OFF_WARP + NWARPS * WARP_STRIDE)
#define SMEM_BYTES  (SMEM_FLOATS * 4)

// ================= kernel 1: zero scratch =================
__global__ void k_zero(int n)
{
    int i = blockIdx.x * blockDim.x + threadIdx.x;
    int tot = n * 10;
    if (i < tot) {
        if (i < n * 9) g_fsum[i] = 0.0f;
        else           g_cnt[i - n * 9] = 0.0f;
    }
}

// ================= kernel 2: edge scatter ==================
// Accumulate per-source-node sum of frames and edge counts.
__global__ void k_edges(const int* __restrict__ row,
                        const float* __restrict__ frames, int E)
{
    int e = blockIdx.x * blockDim.x + threadIdx.x;
    if (e >= E) return;
    int s = row[e];
    const float* f = frames + (size_t)e * 9;
    float* dst = g_fsum + (size_t)s * 9;
#pragma unroll
    for (int k = 0; k < 9; k++)
        atomicAdd(dst + k, f[k]);
    atomicAdd(&g_cnt[s], 1.0f);
}

// ================= kernel 3: fused node kernel =============
__global__ void __launch_bounds__(256, 2)
k_nodes(const float* __restrict__ scalar,
        const float* __restrict__ vector,
        const float* __restrict__ W_down, const float* __restrict__ W_df,
        const float* __restrict__ W_so,   const float* __restrict__ b_so,
        const float* __restrict__ W_up,   const float* __restrict__ W_g,
        const float* __restrict__ b_g,
        float* __restrict__ out1,   // (N, 128) silu(s)
        float* __restrict__ out2,   // (N, 16, 3) vrep
        int N)
{
    extern __shared__ float sm[];
    const int tid  = threadIdx.x;
    const int wid  = tid >> 5;
    const int lane = tid & 31;

    // ---- stage weights into shared (transposed, conflict-free layouts) ----
    for (int i = tid; i < 153 * 128; i += blockDim.x) {
        int o = i / 153, k = i - o * 153;         // coalesced gmem read
        sm[OFF_WSO + k * 129 + o] = W_so[i];
    }
    for (int i = tid; i < 128 * 16; i += blockDim.x) {
        int o = i >> 7, k = i & 127;              // W_g is (16,128)
        sm[OFF_WG + k * 17 + o] = W_g[i];
    }
    for (int i = tid; i < 256; i += blockDim.x) {
        int o = i >> 4, h = i & 15;               // W_up (16,16)
        sm[OFF_WUP + h * 16 + o] = W_up[i];
        int hh = i >> 4, c = i & 15;              // W_down (16,16) [h][c]
        sm[OFF_WDOWN + c * 16 + hh] = W_down[i];
    }
    for (int i = tid; i < 48; i += blockDim.x) {
        int c = i >> 4, k = i & 15;               // W_df (3,16)
        sm[OFF_WDF + k * 3 + c] = W_df[i];
    }
    for (int i = tid; i < 128; i += blockDim.x) sm[OFF_BSO + i] = b_so[i];
    for (int i = tid; i < 16;  i += blockDim.x) sm[OFF_BG  + i] = b_g[i];
    __syncthreads();

    float* merged = sm + OFF_WARP + wid * WARP_STRIDE;   // 160 floats
    float* vec_s  = merged + 160;                        // 48
    float* vh_s   = vec_s + 48;                          // 48 [d*16+h]

    const int warpSlots = gridDim.x * NWARPS;
    for (int n = blockIdx.x * NWARPS + wid; n < N; n += warpSlots) {
        // ---- load node vector (16,3) = 48 floats ----
        const float* vptr = vector + (size_t)n * 48;
        vec_s[lane] = vptr[lane];
        if (lane < 16) vec_s[32 + lane] = vptr[32 + lane];
        __syncwarp();

        // ---- vh (lanes 0..15), vdf+sh (lanes 16..18) ----
        if (lane < 16) {
            const int h = lane;
            float vh0 = 0.f, vh1 = 0.f, vh2 = 0.f;
#pragma unroll
            for (int c = 0; c < 16; c++) {
                float w = sm[OFF_WDOWN + c * 16 + h];
                vh0 = fmaf(w, vec_s[c * 3 + 0], vh0);
                vh1 = fmaf(w, vec_s[c * 3 + 1], vh1);
                vh2 = fmaf(w, vec_s[c * 3 + 2], vh2);
            }
            merged[128 + h] = sqrtf(vh0 * vh0 + vh1 * vh1 + vh2 * vh2 + EPS);
            vh_s[h]      = vh0;
            vh_s[16 + h] = vh1;
            vh_s[32 + h] = vh2;
        } else if (lane < 19) {
            const int c = lane - 16;
            float d0 = 0.f, d1 = 0.f, d2 = 0.f;
#pragma unroll
            for (int k = 0; k < 16; k++) {
                float w = sm[OFF_WDF + k * 3 + c];
                d0 = fmaf(w, vec_s[k * 3 + 0], d0);
                d1 = fmaf(w, vec_s[k * 3 + 1], d1);
                d2 = fmaf(w, vec_s[k * 3 + 2], d2);
            }
            float inv = 1.0f / fmaxf(g_cnt[n], 1.0f);
            const float* fs = g_fsum + (size_t)n * 9;
#pragma unroll
            for (int i2 = 0; i2 < 3; i2++) {
                float v = fs[i2 * 3 + 0] * d0 + fs[i2 * 3 + 1] * d1
                        + fs[i2 * 3 + 2] * d2;
                merged[144 + c * 3 + i2] = v * inv;
            }
        }
        // ---- scalar part of merged (all lanes, float4 coalesced) ----
        {
            const float4 s4 = ((const float4*)(scalar + (size_t)n * 128))[lane];
            ((float4*)merged)[lane] = s4;
        }
        __syncwarp();

        // ---- main GEMM: s[o] = merged(153) . W_so[o,:] + b ----
        float a0 = sm[OFF_BSO + lane];
        float a1 = sm[OFF_BSO + lane + 32];
        float a2 = sm[OFF_BSO + lane + 64];
        float a3 = sm[OFF_BSO + lane + 96];
#pragma unroll 9
        for (int k = 0; k < 153; k++) {
            float m = merged[k];
            const float* wr = sm + OFF_WSO + k * 129;
            a0 = fmaf(m, wr[lane],      a0);
            a1 = fmaf(m, wr[lane + 32], a1);
            a2 = fmaf(m, wr[lane + 64], a2);
            a3 = fmaf(m, wr[lane + 96], a3);
        }
        // silu
        float s0 = a0 / (1.0f + expf(-a0));
        float s1 = a1 / (1.0f + expf(-a1));
        float s2 = a2 / (1.0f + expf(-a2));
        float s3 = a3 / (1.0f + expf(-a3));
        float* o1 = out1 + (size_t)n * 128;
        o1[lane]      = s0;
        o1[lane + 32] = s1;
        o1[lane + 64] = s2;
        o1[lane + 96] = s3;
        __syncwarp();
        merged[lane]      = s0;   // reuse merged as silu buffer
        merged[lane + 32] = s1;
        merged[lane + 64] = s2;
        merged[lane + 96] = s3;
        __syncwarp();

        // ---- gate + vrep (lanes 0..15, o = lane) ----
        if (lane < 16) {
            const int o = lane;
            float g = sm[OFF_BG + o];
#pragma unroll 8
            for (int k = 0; k < 128; k++)
                g = fmaf(merged[k], sm[OFF_WG + k * 17 + o], g);
            float sg = 1.0f / (1.0f + expf(-g));
            float r0 = 0.f, r1 = 0.f, r2 = 0.f;
#pragma unroll
            for (int h = 0; h < 16; h++) {
                float w = sm[OFF_WUP + h * 16 + o];
                r0 = fmaf(w, vh_s[h],      r0);
                r1 = fmaf(w, vh_s[16 + h], r1);
                r2 = fmaf(w, vh_s[32 + h], r2);
            }
            float* od = out2 + (size_t)n * 48 + o * 3;
            od[0] = r0 * sg;
            od[1] = r1 * sg;
            od[2] = r2 * sg;
        }
        __syncwarp();
    }
}

// ================= launch =================
extern "C" void kernel_launch(void* const* d_in, const int* in_sizes, int n_in,
                              void* d_out, int out_size)
{
    const float* scalar  = (const float*)d_in[0];
    const float* vector  = (const float*)d_in[1];
    const int*   eidx    = (const int*)  d_in[2];
    const float* frames  = (const float*)d_in[3];
    const float* W_down  = (const float*)d_in[4];
    const float* W_df    = (const float*)d_in[5];
    const float* W_so    = (const float*)d_in[6];
    const float* b_so    = (const float*)d_in[7];
    const float* W_up    = (const float*)d_in[8];
    const float* W_g     = (const float*)d_in[9];
    const float* b_g     = (const float*)d_in[10];

    const int N = in_sizes[0] / S_IN;        // 50000
    const int E = in_sizes[2] / 2;           // 1.6M
    const int* row = eidx;                    // edge_index[0]

    float* out1 = (float*)d_out;              // (N,128)
    float* out2 = out1 + (size_t)N * S_OUT;   // (N,16,3)

    cudaFuncSetAttribute(k_nodes, cudaFuncAttributeMaxDynamicSharedMemorySize,
                         SMEM_BYTES);

    k_zero<<<(N * 10 + 255) / 256, 256>>>(N);
    k_edges<<<(E + 255) / 256, 256>>>(row, frames, E);
    k_nodes<<<304, 256, SMEM_BYTES>>>(scalar, vector, W_down, W_df, W_so, b_so,
                                      W_up, W_g, b_g, out1, out2, N);
}

// round 3
// speedup vs baseline: 1.9281x; 1.9281x over previous
#include <cuda_runtime.h>
#include <math.h>

#define S_IN   128
#define V_IN   16
#define HID    16
#define SVO    3
#define S_OUT  128
#define V_OUT  16
#define MAXN   50000
#define EPS    1e-8f

// ---- scratch: per-node accumulator, 12 floats (3 x float4):
//      [0..8]=sum of frames, [9]=edge count, [10,11]=pad
__device__ float4 g_acc[MAXN * 3];

// ---- shared layout (floats) for node kernel ----
#define OFF_WSO    0                       // [k*129 + o], k<153, o<128
#define SZ_WSO     19740
#define OFF_WG     (OFF_WSO + SZ_WSO)      // [k*17 + o], k<128, o<16
#define SZ_WG      2176
#define OFF_WUP    (OFF_WG + SZ_WG)        // [h*16 + o]
#define SZ_WUP     256
#define OFF_WDOWN  (OFF_WUP + SZ_WUP)      // [c*16 + h]
#define SZ_WDOWN   256
#define OFF_WDF    (OFF_WDOWN + SZ_WDOWN)  // [k*3 + c]
#define SZ_WDF     48
#define OFF_BSO    (OFF_WDF + SZ_WDF)
#define SZ_BSO     128
#define OFF_BG     (OFF_BSO + SZ_BSO)
#define SZ_BG      16
#define OFF_WARP   (OFF_BG + SZ_BG + 12)   // pad to 16B boundary (22632*4 % 16 == 0... ensure)
// per-warp buffer: merged 8*160 = 1280 (reused as msil[128][9] = 1152 in epilogue)
//                  vh 8*48 = 384, vec 48   -> 1712 floats
#define MG_SZ      1280
#define VH_OFF     MG_SZ
#define VEC_OFF    (MG_SZ + 384)
#define WARP_STRIDE 1712
#define NWARPS     16
#define NPW        8                        // nodes per warp
#define SMEM_FLOATS (OFF_WARP + NWARPS * WARP_STRIDE)
#define SMEM_BYTES  (SMEM_FLOATS * 4)

// ================= kernel 1: zero scratch =================
__global__ void k_zero(void)
{
    int i = blockIdx.x * blockDim.x + threadIdx.x;
    if (i < MAXN * 3) g_acc[i] = make_float4(0.f, 0.f, 0.f, 0.f);
}

// ================= kernel 2: edge scatter (vector RED) =====
__global__ void __launch_bounds__(256)
k_edges(const int* __restrict__ row, const float* __restrict__ frames, int E)
{
    __shared__ float buf[8][288];
    const int w = threadIdx.x >> 5, lane = threadIdx.x & 31;
    const long e0 = ((long)blockIdx.x * 8 + w) * 32;
    if (e0 >= E) return;
    const int cnt = (int)min((long)32, (long)E - e0);
    const float* src = frames + e0 * 9;
    for (int i = lane; i < cnt * 9; i += 32) buf[w][i] = src[i];
    int s = (lane < cnt) ? row[e0 + lane] : -1;
    __syncwarp();
    if (s >= 0) {
        const float* f = &buf[w][lane * 9];
        float* dst = (float*)(g_acc + (size_t)s * 3);
        asm volatile("red.global.add.v4.f32 [%0], {%1,%2,%3,%4};"
                     :: "l"(dst), "f"(f[0]), "f"(f[1]), "f"(f[2]), "f"(f[3]) : "memory");
        asm volatile("red.global.add.v4.f32 [%0], {%1,%2,%3,%4};"
                     :: "l"(dst + 4), "f"(f[4]), "f"(f[5]), "f"(f[6]), "f"(f[7]) : "memory");
        asm volatile("red.global.add.v4.f32 [%0], {%1,%2,%3,%4};"
                     :: "l"(dst + 8), "f"(f[8]), "f"(1.0f), "f"(0.0f), "f"(0.0f) : "memory");
    }
}

// ================= kernel 3: fused node kernel =============
__global__ void __launch_bounds__(512, 1)
k_nodes(const float* __restrict__ scalar,
        const float* __restrict__ vector,
        const float* __restrict__ W_down, const float* __restrict__ W_df,
        const float* __restrict__ W_so,   const float* __restrict__ b_so,
        const float* __restrict__ W_up,   const float* __restrict__ W_g,
        const float* __restrict__ b_g,
        float* __restrict__ out1, float* __restrict__ out2, int N)
{
    extern __shared__ float sm[];
    const int tid  = threadIdx.x;
    const int wid  = tid >> 5;
    const int lane = tid & 31;

    // ---- stage weights (transposed, conflict-free) ----
    for (int i = tid; i < 153 * 128; i += blockDim.x) {
        int o = i / 153, k = i - o * 153;
        sm[OFF_WSO + k * 129 + o] = W_so[i];
    }
    for (int i = tid; i < 128 * 16; i += blockDim.x) {
        int o = i >> 7, k = i & 127;
        sm[OFF_WG + k * 17 + o] = W_g[i];
    }
    for (int i = tid; i < 256; i += blockDim.x) {
        int o = i >> 4, h = i & 15;
        sm[OFF_WUP + h * 16 + o] = W_up[i];
        sm[OFF_WDOWN + h * 16 + o] = W_down[i];  // here o plays role of h-index: [c*16+h] with c=i>>4? careful
    }
    // fix W_down layout: W_down is (HID,V_IN) row-major: W_down[h][c]; we want sm[c*16+h]
    __syncthreads();
    for (int i = tid; i < 256; i += blockDim.x) {
        int h = i >> 4, c = i & 15;
        sm[OFF_WDOWN + c * 16 + h] = W_down[i];
    }
    for (int i = tid; i < 48; i += blockDim.x) {
        int c = i >> 4, k = i & 15;   // W_df (3,16)
        sm[OFF_WDF + k * 3 + c] = W_df[i];
    }
    for (int i = tid; i < 128; i += blockDim.x) sm[OFF_BSO + i] = b_so[i];
    for (int i = tid; i < 16;  i += blockDim.x) sm[OFF_BG  + i] = b_g[i];
    __syncthreads();

    float* wb   = sm + OFF_WARP + wid * WARP_STRIDE;
    float* vecb = wb + VEC_OFF;
    const int h16 = lane >> 4;        // 0/1
    const int o16 = lane & 15;

    // preload W_up column o16 into registers
    float wu[16];
#pragma unroll
    for (int hh = 0; hh < 16; hh++) wu[hh] = sm[OFF_WUP + hh * 16 + o16];

    const float b0 = sm[OFF_BSO + lane];
    const float b1 = sm[OFF_BSO + lane + 32];
    const float b2 = sm[OFF_BSO + lane + 64];
    const float b3 = sm[OFF_BSO + lane + 96];
    const float bg = sm[OFF_BG + o16];

    const int iterStride = gridDim.x * NWARPS * NPW;
    for (int base = (blockIdx.x * NWARPS + wid) * NPW; base < N; base += iterStride) {
        const int nv = min(NPW, N - base);   // valid nodes this group (uniform per warp)

        // ---------- prep: per node j ----------
        for (int j = 0; j < nv; j++) {
            const int n = base + j;
            const float* vptr = vector + (size_t)n * 48;
            vecb[lane] = vptr[lane];
            if (lane < 16) vecb[32 + lane] = vptr[32 + lane];
            __syncwarp();
            float* mg = wb + j * 160;
            float* vh = wb + VH_OFF + j * 48;
            if (lane < 16) {
                const int h = lane;
                float vh0 = 0.f, vh1 = 0.f, vh2 = 0.f;
#pragma unroll
                for (int c = 0; c < 16; c++) {
                    float w = sm[OFF_WDOWN + c * 16 + h];
                    vh0 = fmaf(w, vecb[c * 3 + 0], vh0);
                    vh1 = fmaf(w, vecb[c * 3 + 1], vh1);
                    vh2 = fmaf(w, vecb[c * 3 + 2], vh2);
                }
                mg[128 + h] = sqrtf(vh0 * vh0 + vh1 * vh1 + vh2 * vh2 + EPS);
                vh[h] = vh0; vh[16 + h] = vh1; vh[32 + h] = vh2;
            } else if (lane < 19) {
                const int c = lane - 16;
                float d0 = 0.f, d1 = 0.f, d2 = 0.f;
#pragma unroll
                for (int k = 0; k < 16; k++) {
                    float w = sm[OFF_WDF + k * 3 + c];
                    d0 = fmaf(w, vecb[k * 3 + 0], d0);
                    d1 = fmaf(w, vecb[k * 3 + 1], d1);
                    d2 = fmaf(w, vecb[k * 3 + 2], d2);
                }
                float4 q0 = g_acc[(size_t)n * 3 + 0];
                float4 q1 = g_acc[(size_t)n * 3 + 1];
                float4 q2 = g_acc[(size_t)n * 3 + 2];
                float inv = 1.0f / fmaxf(q2.y, 1.0f);
                mg[144 + c * 3 + 0] = (q0.x * d0 + q0.y * d1 + q0.z * d2) * inv;
                mg[144 + c * 3 + 1] = (q0.w * d0 + q1.x * d1 + q1.y * d2) * inv;
                mg[144 + c * 3 + 2] = (q1.z * d0 + q1.w * d1 + q2.x * d2) * inv;
            }
            const float4 s4 = ((const float4*)(scalar + (size_t)n * 128))[lane];
            ((float4*)mg)[lane] = s4;
            __syncwarp();
        }

        // ---------- main GEMM: 8 nodes x 128 outputs over K=153 ----------
        float a[NPW][4];
#pragma unroll
        for (int j = 0; j < NPW; j++) { a[j][0] = b0; a[j][1] = b1; a[j][2] = b2; a[j][3] = b3; }

#pragma unroll 9
        for (int k = 0; k < 153; k++) {
            const float* wr = sm + OFF_WSO + k * 129;
            const float w0 = wr[lane];
            const float w1 = wr[lane + 32];
            const float w2 = wr[lane + 64];
            const float w3 = wr[lane + 96];
#pragma unroll
            for (int j = 0; j < NPW; j++) {
                const float m = wb[j * 160 + k];
                a[j][0] = fmaf(m, w0, a[j][0]);
                a[j][1] = fmaf(m, w1, a[j][1]);
                a[j][2] = fmaf(m, w2, a[j][2]);
                a[j][3] = fmaf(m, w3, a[j][3]);
            }
        }
        __syncwarp();

        // ---------- silu, write out1 + packed msil[k][9] ----------
        float* msil = wb;    // overwrites merged region
#pragma unroll
        for (int j = 0; j < NPW; j++) {
            float s0 = a[j][0] / (1.0f + __expf(-a[j][0]));
            float s1 = a[j][1] / (1.0f + __expf(-a[j][1]));
            float s2 = a[j][2] / (1.0f + __expf(-a[j][2]));
            float s3 = a[j][3] / (1.0f + __expf(-a[j][3]));
            msil[lane * 9 + j]        = s0;
            msil[(lane + 32) * 9 + j] = s1;
            msil[(lane + 64) * 9 + j] = s2;
            msil[(lane + 96) * 9 + j] = s3;
            if (base + j < N) {
                float* o1 = out1 + (size_t)(base + j) * 128;
                o1[lane] = s0; o1[lane + 32] = s1; o1[lane + 64] = s2; o1[lane + 96] = s3;
            }
        }
        __syncwarp();

        // ---------- gate GEMM: 4 nodes per lane (j = h16 + 2t) ----------
        float g[4];
#pragma unroll
        for (int t = 0; t < 4; t++) g[t] = bg;
#pragma unroll 8
        for (int k = 0; k < 128; k++) {
            const float wg = sm[OFF_WG + k * 17 + o16];
            const float* mk = msil + k * 9 + h16;
            g[0] = fmaf(mk[0], wg, g[0]);
            g[1] = fmaf(mk[2], wg, g[1]);
            g[2] = fmaf(mk[4], wg, g[2]);
            g[3] = fmaf(mk[6], wg, g[3]);
        }

        // ---------- vrep ----------
#pragma unroll
        for (int t = 0; t < 4; t++) {
            const int j = h16 + 2 * t;
            const int n = base + j;
            const float sg = 1.0f / (1.0f + __expf(-g[t]));
            const float* vh = wb + VH_OFF + j * 48;
            float r0 = 0.f, r1 = 0.f, r2 = 0.f;
#pragma unroll
            for (int hh = 0; hh < 16; hh++) {
                r0 = fmaf(wu[hh], vh[hh],      r0);
                r1 = fmaf(wu[hh], vh[16 + hh], r1);
                r2 = fmaf(wu[hh], vh[32 + hh], r2);
            }
            if (n < N) {
                float* od = out2 + (size_t)n * 48 + o16 * 3;
                od[0] = r0 * sg; od[1] = r1 * sg; od[2] = r2 * sg;
            }
        }
        __syncwarp();
    }
}

// ================= launch =================
extern "C" void kernel_launch(void* const* d_in, const int* in_sizes, int n_in,
                              void* d_out, int out_size)
{
    const float* scalar  = (const float*)d_in[0];
    const float* vector  = (const float*)d_in[1];
    const int*   eidx    = (const int*)  d_in[2];
    const float* frames  = (const float*)d_in[3];
    const float* W_down  = (const float*)d_in[4];
    const float* W_df    = (const float*)d_in[5];
    const float* W_so    = (const float*)d_in[6];
    const float* b_so    = (const float*)d_in[7];
    const float* W_up    = (const float*)d_in[8];
    const float* W_g     = (const float*)d_in[9];
    const float* b_g     = (const float*)d_in[10];

    const int N = in_sizes[0] / S_IN;
    const int E = in_sizes[2] / 2;
    const int* row = eidx;

    float* out1 = (float*)d_out;
    float* out2 = out1 + (size_t)N * S_OUT;

    cudaFuncSetAttribute(k_nodes, cudaFuncAttributeMaxDynamicSharedMemorySize,
                         SMEM_BYTES);

    k_zero<<<(MAXN * 3 + 255) / 256, 256>>>();
    k_edges<<<(E + 255) / 256, 256>>>(row, frames, E);
    k_nodes<<<148, 512, SMEM_BYTES>>>(scalar, vector, W_down, W_df, W_so, b_so,
                                      W_up, W_g, b_g, out1, out2, N);
}

// round 4
// speedup vs baseline: 2.0713x; 1.0743x over previous
#include <cuda_runtime.h>
#include <math.h>

#define MAXN 50000
#define EPS  1e-8f

typedef unsigned long long ull;

// ---- scratch: per-node accumulator, 12 floats: [0..8]=frame sum, [9]=count
__device__ float4 g_acc[MAXN * 3];

// ---- packed f32x2 helpers (FFMA2 — only reachable via PTX) ----
__device__ __forceinline__ ull pk2(float lo, float hi) {
    ull r; asm("mov.b64 %0, {%1,%2};" : "=l"(r) : "f"(lo), "f"(hi)); return r;
}
__device__ __forceinline__ void unpk2(ull v, float& lo, float& hi) {
    asm("mov.b64 {%0,%1}, %2;" : "=f"(lo), "=f"(hi) : "l"(v));
}
__device__ __forceinline__ ull ffma2(ull a, ull b, ull c) {
    ull d; asm("fma.rn.f32x2 %0, %1, %2, %3;" : "=l"(d) : "l"(a), "l"(b), "l"(c));
    return d;
}

// ---- shared layout (floats) ----
#define OFF_WSO    0                       // [k*132 + o], k<153, o<128 (LDS.128 per lane)
#define SZ_WSO     20200                   // 153*132 = 20196, padded
#define OFF_WG     (OFF_WSO + SZ_WSO)      // [k*17 + o16]
#define SZ_WG      2176
#define OFF_WUP    (OFF_WG + SZ_WG)        // [h*16 + o]
#define SZ_WUP     256
#define OFF_WDOWN  (OFF_WUP + SZ_WUP)      // [c*16 + h]
#define SZ_WDOWN   256
#define OFF_WDF    (OFF_WDOWN + SZ_WDOWN)  // [k*3 + c]
#define SZ_WDF     48
#define OFF_BSO    (OFF_WDF + SZ_WDF)
#define SZ_BSO     128
#define OFF_BG     (OFF_BSO + SZ_BSO)
#define SZ_BG      16
#define OFF_WARP   (OFF_BG + SZ_BG)        // 23080 (16B aligned)
// per-warp: mgT [k*10 + j] k<153 -> 1536 (reused as msil[o*10+j] in epilogue)
//           vh 8*48 = 384, vec 48
#define MGT_SZ     1536
#define VH_OFF     MGT_SZ
#define VEC_OFF    (MGT_SZ + 384)
#define WARP_STRIDE 1968
#define NWARPS     16
#define NPW        8
#define SMEM_FLOATS (OFF_WARP + NWARPS * WARP_STRIDE)
#define SMEM_BYTES  (SMEM_FLOATS * 4)

// ================= kernel 1: zero scratch =================
__global__ void k_zero(void)
{
    int i = blockIdx.x * blockDim.x + threadIdx.x;
    if (i < MAXN * 3) g_acc[i] = make_float4(0.f, 0.f, 0.f, 0.f);
}

// ================= kernel 2: edge scatter (vector RED) =====
__global__ void __launch_bounds__(256)
k_edges(const int* __restrict__ row, const float* __restrict__ frames, int E)
{
    __shared__ float buf[8][288];
    const int w = threadIdx.x >> 5, lane = threadIdx.x & 31;
    const long e0 = ((long)blockIdx.x * 8 + w) * 32;
    if (e0 >= E) return;
    const int cnt = (int)min((long)32, (long)E - e0);
    const float* src = frames + e0 * 9;
    for (int i = lane; i < cnt * 9; i += 32) buf[w][i] = src[i];
    int s = (lane < cnt) ? row[e0 + lane] : -1;
    __syncwarp();
    if (s >= 0) {
        const float* f = &buf[w][lane * 9];
        float* dst = (float*)(g_acc + (size_t)s * 3);
        asm volatile("red.global.add.v4.f32 [%0], {%1,%2,%3,%4};"
                     :: "l"(dst), "f"(f[0]), "f"(f[1]), "f"(f[2]), "f"(f[3]) : "memory");
        asm volatile("red.global.add.v4.f32 [%0], {%1,%2,%3,%4};"
                     :: "l"(dst + 4), "f"(f[4]), "f"(f[5]), "f"(f[6]), "f"(f[7]) : "memory");
        asm volatile("red.global.add.v4.f32 [%0], {%1,%2,%3,%4};"
                     :: "l"(dst + 8), "f"(f[8]), "f"(1.0f), "f"(0.0f), "f"(0.0f) : "memory");
    }
}

// ================= kernel 3: fused node kernel =============
__global__ void __launch_bounds__(512, 1)
k_nodes(const float* __restrict__ scalar,
        const float* __restrict__ vector,
        const float* __restrict__ W_down, const float* __restrict__ W_df,
        const float* __restrict__ W_so,   const float* __restrict__ b_so,
        const float* __restrict__ W_up,   const float* __restrict__ W_g,
        const float* __restrict__ b_g,
        float* __restrict__ out1, float* __restrict__ out2, int N)
{
    extern __shared__ float sm[];
    const int tid  = threadIdx.x;
    const int wid  = tid >> 5;
    const int lane = tid & 31;
    const int lane4 = lane << 2;

    // ---- stage weights ----
    for (int i = tid; i < 153 * 128; i += blockDim.x) {
        int o = i / 153, k = i - o * 153;
        sm[OFF_WSO + k * 132 + o] = W_so[i];
    }
    for (int i = tid; i < 128 * 16; i += blockDim.x) {
        int o = i >> 7, k = i & 127;
        sm[OFF_WG + k * 17 + o] = W_g[i];
    }
    for (int i = tid; i < 256; i += blockDim.x) {
        int h = i >> 4, c = i & 15;
        sm[OFF_WUP + c * 16 + h] = W_up[i];     // W_up (16,16): [hid*16 + o] => o=h? careful
    }
    __syncthreads();
    // redo with explicit roles: W_up[o][h] row-major -> want sm[h*16 + o]
    for (int i = tid; i < 256; i += blockDim.x) {
        int o = i >> 4, h = i & 15;
        sm[OFF_WUP + h * 16 + o] = W_up[i];
        // W_down[h][c] -> sm[c*16+h]
        int hh = i >> 4, c = i & 15;
        sm[OFF_WDOWN + c * 16 + hh] = W_down[i];
    }
    for (int i = tid; i < 48; i += blockDim.x) {
        int c = i >> 4, k = i & 15;   // W_df (3,16)
        sm[OFF_WDF + k * 3 + c] = W_df[i];
    }
    for (int i = tid; i < 128; i += blockDim.x) sm[OFF_BSO + i] = b_so[i];
    for (int i = tid; i < 16;  i += blockDim.x) sm[OFF_BG  + i] = b_g[i];
    __syncthreads();

    float* wb   = sm + OFF_WARP + wid * WARP_STRIDE;
    float* mgT  = wb;                 // [k*10 + j]
    float* vhb  = wb + VH_OFF;        // [j*48 + d*16 + h]
    float* vecb = wb + VEC_OFF;

    const int o16 = lane & 15;
    const int h16 = lane >> 4;

    float wu[16];
#pragma unroll
    for (int hh = 0; hh < 16; hh++) wu[hh] = sm[OFF_WUP + hh * 16 + o16];

    const float4 bb = *(const float4*)&sm[OFF_BSO + lane4];
    const float  bgv = sm[OFF_BG + o16];

    const int iterStride = gridDim.x * NWARPS * NPW;
    for (int base = (blockIdx.x * NWARPS + wid) * NPW; base < N; base += iterStride) {
        const int nv = min(NPW, N - base);

        // ---------- prep: build mgT (transposed merged) ----------
        for (int j = 0; j < nv; j++) {
            const int n = base + j;
            const float* vptr = vector + (size_t)n * 48;
            vecb[lane] = vptr[lane];
            if (lane < 16) vecb[32 + lane] = vptr[32 + lane];
            __syncwarp();
            if (lane < 16) {
                const int h = lane;
                float vh0 = 0.f, vh1 = 0.f, vh2 = 0.f;
#pragma unroll
                for (int c = 0; c < 16; c++) {
                    float w = sm[OFF_WDOWN + c * 16 + h];
                    vh0 = fmaf(w, vecb[c * 3 + 0], vh0);
                    vh1 = fmaf(w, vecb[c * 3 + 1], vh1);
                    vh2 = fmaf(w, vecb[c * 3 + 2], vh2);
                }
                mgT[(128 + h) * 10 + j] = sqrtf(vh0 * vh0 + vh1 * vh1 + vh2 * vh2 + EPS);
                float* vh = vhb + j * 48;
                vh[h] = vh0; vh[16 + h] = vh1; vh[32 + h] = vh2;
            } else if (lane < 19) {
                const int c = lane - 16;
                float d0 = 0.f, d1 = 0.f, d2 = 0.f;
#pragma unroll
                for (int k = 0; k < 16; k++) {
                    float w = sm[OFF_WDF + k * 3 + c];
                    d0 = fmaf(w, vecb[k * 3 + 0], d0);
                    d1 = fmaf(w, vecb[k * 3 + 1], d1);
                    d2 = fmaf(w, vecb[k * 3 + 2], d2);
                }
                float4 q0 = g_acc[(size_t)n * 3 + 0];
                float4 q1 = g_acc[(size_t)n * 3 + 1];
                float4 q2 = g_acc[(size_t)n * 3 + 2];
                float inv = 1.0f / fmaxf(q2.y, 1.0f);
                mgT[(144 + c * 3 + 0) * 10 + j] = (q0.x * d0 + q0.y * d1 + q0.z * d2) * inv;
                mgT[(144 + c * 3 + 1) * 10 + j] = (q0.w * d0 + q1.x * d1 + q1.y * d2) * inv;
                mgT[(144 + c * 3 + 2) * 10 + j] = (q1.z * d0 + q1.w * d1 + q2.x * d2) * inv;
            }
            // scalar features, transposed write (2-way conflicts only)
#pragma unroll
            for (int i = 0; i < 4; i++) {
                float s = scalar[(size_t)n * 128 + lane + 32 * i];
                mgT[(lane + 32 * i) * 10 + j] = s;
            }
            __syncwarp();
        }

        // ---------- main GEMM: FFMA2, 8 nodes x 4 outputs/lane over K=153 ----------
        ull a0_0 = pk2(bb.x, bb.x), a0_1 = a0_0, a0_2 = a0_0, a0_3 = a0_0;
        ull a1_0 = pk2(bb.y, bb.y), a1_1 = a1_0, a1_2 = a1_0, a1_3 = a1_0;
        ull a2_0 = pk2(bb.z, bb.z), a2_1 = a2_0, a2_2 = a2_0, a2_3 = a2_0;
        ull a3_0 = pk2(bb.w, bb.w), a3_1 = a3_0, a3_2 = a3_0, a3_3 = a3_0;

#pragma unroll 3
        for (int k = 0; k < 153; k++) {
            const float4 w4 = *(const float4*)&sm[OFF_WSO + k * 132 + lane4];
            const ull w0 = pk2(w4.x, w4.x);
            const ull w1 = pk2(w4.y, w4.y);
            const ull w2 = pk2(w4.z, w4.z);
            const ull w3 = pk2(w4.w, w4.w);
            const ull* mrow = (const ull*)(mgT + k * 10);
            const ull m0 = mrow[0], m1 = mrow[1], m2 = mrow[2], m3 = mrow[3];
            a0_0 = ffma2(w0, m0, a0_0); a0_1 = ffma2(w0, m1, a0_1);
            a0_2 = ffma2(w0, m2, a0_2); a0_3 = ffma2(w0, m3, a0_3);
            a1_0 = ffma2(w1, m0, a1_0); a1_1 = ffma2(w1, m1, a1_1);
            a1_2 = ffma2(w1, m2, a1_2); a1_3 = ffma2(w1, m3, a1_3);
            a2_0 = ffma2(w2, m0, a2_0); a2_1 = ffma2(w2, m1, a2_1);
            a2_2 = ffma2(w2, m2, a2_2); a2_3 = ffma2(w2, m3, a2_3);
            a3_0 = ffma2(w3, m0, a3_0); a3_1 = ffma2(w3, m1, a3_1);
            a3_2 = ffma2(w3, m2, a3_2); a3_3 = ffma2(w3, m3, a3_3);
        }
        __syncwarp();

        // ---------- silu + out1 (STG.128) + msil [o*10 + j] ----------
        float sil[4][8];
        {
            ull A[4][4] = {{a0_0,a0_1,a0_2,a0_3},{a1_0,a1_1,a1_2,a1_3},
                           {a2_0,a2_1,a2_2,a2_3},{a3_0,a3_1,a3_2,a3_3}};
#pragma unroll
            for (int i = 0; i < 4; i++)
#pragma unroll
                for (int t = 0; t < 4; t++) {
                    float lo, hi; unpk2(A[i][t], lo, hi);
                    sil[i][2*t]   = lo / (1.0f + __expf(-lo));
                    sil[i][2*t+1] = hi / (1.0f + __expf(-hi));
                }
        }
        float* msil = wb;   // overwrites mgT (done with it)
#pragma unroll
        for (int j = 0; j < NPW; j++) {
            if (base + j < N) {
                float4 o4 = make_float4(sil[0][j], sil[1][j], sil[2][j], sil[3][j]);
                *(float4*)(out1 + (size_t)(base + j) * 128 + lane4) = o4;
            }
#pragma unroll
            for (int i = 0; i < 4; i++)
                msil[(lane4 + i) * 10 + j] = sil[i][j];
        }
        __syncwarp();

        // ---------- gate GEMM (FFMA2): lane handles o16, nodes 4*h16+{0..3} ----------
        ull g01 = pk2(bgv, bgv), g23 = g01;
#pragma unroll 4
        for (int k = 0; k < 128; k++) {
            const float wg = sm[OFF_WG + k * 17 + o16];
            const ull wgp = pk2(wg, wg);
            const ull* mp = (const ull*)(msil + k * 10 + 4 * h16);
            g01 = ffma2(wgp, mp[0], g01);
            g23 = ffma2(wgp, mp[1], g23);
        }
        float gv[4];
        unpk2(g01, gv[0], gv[1]);
        unpk2(g23, gv[2], gv[3]);

        // ---------- vrep ----------
#pragma unroll
        for (int t = 0; t < 4; t++) {
            const int j = 4 * h16 + t;
            const int n = base + j;
            const float sg = 1.0f / (1.0f + __expf(-gv[t]));
            const float* vh = vhb + j * 48;
            float r0 = 0.f, r1 = 0.f, r2 = 0.f;
#pragma unroll
            for (int hh = 0; hh < 16; hh++) {
                r0 = fmaf(wu[hh], vh[hh],      r0);
                r1 = fmaf(wu[hh], vh[16 + hh], r1);
                r2 = fmaf(wu[hh], vh[32 + hh], r2);
            }
            if (n < N) {
                float* od = out2 + (size_t)n * 48 + o16 * 3;
                od[0] = r0 * sg; od[1] = r1 * sg; od[2] = r2 * sg;
            }
        }
        __syncwarp();
    }
}

// ================= launch =================
extern "C" void kernel_launch(void* const* d_in, const int* in_sizes, int n_in,
                              void* d_out, int out_size)
{
    const float* scalar  = (const float*)d_in[0];
    const float* vector  = (const float*)d_in[1];
    const int*   eidx    = (const int*)  d_in[2];
    const float* frames  = (const float*)d_in[3];
    const float* W_down  = (const float*)d_in[4];
    const float* W_df    = (const float*)d_in[5];
    const float* W_so    = (const float*)d_in[6];
    const float* b_so    = (const float*)d_in[7];
    const float* W_up    = (const float*)d_in[8];
    const float* W_g     = (const float*)d_in[9];
    const float* b_g     = (const float*)d_in[10];

    const int N = in_sizes[0] / 128;
    const int E = in_sizes[2] / 2;
    const int* row = eidx;

    float* out1 = (float*)d_out;
    float* out2 = out1 + (size_t)N * 128;

    cudaFuncSetAttribute(k_nodes, cudaFuncAttributeMaxDynamicSharedMemorySize,
                         SMEM_BYTES);

    k_zero<<<(MAXN * 3 + 255) / 256, 256>>>();
    k_edges<<<(E + 255) / 256, 256>>>(row, frames, E);
    k_nodes<<<148, 512, SMEM_BYTES>>>(scalar, vector, W_down, W_df, W_so, b_so,
                                      W_up, W_g, b_g, out1, out2, N);
}

// round 5
// speedup vs baseline: 2.7465x; 1.3260x over previous
#include <cuda_runtime.h>
#include <math.h>

#define MAXN 50000
#define EPS  1e-8f

typedef unsigned long long ull;

// ---- scratch ----
__device__ float4 g_acc[MAXN * 3];   // [0..8]=frame sum, [9]=count, pad
__device__ int    g_ticket;

// ---- packed f32x2 helpers ----
__device__ __forceinline__ ull pk2(float lo, float hi) {
    ull r; asm("mov.b64 %0, {%1,%2};" : "=l"(r) : "f"(lo), "f"(hi)); return r;
}
__device__ __forceinline__ void unpk2(ull v, float& lo, float& hi) {
    asm("mov.b64 {%0,%1}, %2;" : "=f"(lo), "=f"(hi) : "l"(v));
}
__device__ __forceinline__ ull ffma2(ull a, ull b, ull c) {
    ull d; asm("fma.rn.f32x2 %0, %1, %2, %3;" : "=l"(d) : "l"(a), "l"(b), "l"(c));
    return d;
}

// ---- shared layout (floats) ----
#define OFF_WSO    0                        // [k*132 + o]
#define SZ_WSO     20200
#define OFF_WG     (OFF_WSO + SZ_WSO)       // [o*134 + k]  (conflict-free LDS.64 pairs)
#define SZ_WG      2144
#define OFF_WUP    (OFF_WG + SZ_WG)         // [h*16 + o]
#define SZ_WUP     256
#define OFF_WDOWN  (OFF_WUP + SZ_WUP)       // [c*16 + h]
#define SZ_WDOWN   256
#define OFF_WDF    (OFF_WDOWN + SZ_WDOWN)   // [k*3 + c]
#define SZ_WDF     48
#define OFF_BSO    (OFF_WDF + SZ_WDF)
#define SZ_BSO     128
#define OFF_BG     (OFF_BSO + SZ_BSO)
#define SZ_BG      16
#define OFF_WARP   (OFF_BG + SZ_BG)         // even word offset -> 8B aligned
// per-warp: mgT[k*10+j] k<153 (1536; first 384 floats double as vec buffer,
//           reused as msil[j*132+k] (1056) in epilogue), vhb 384
#define MGT_SZ     1536
#define VH_OFF     MGT_SZ
#define WARP_STRIDE 1920
#define NWARPS     16
#define NPW        8
#define SMEM_FLOATS (OFF_WARP + NWARPS * WARP_STRIDE)
#define SMEM_BYTES  (SMEM_FLOATS * 4)

// ================= kernel 1: zero scratch =================
__global__ void k_zero(void)
{
    int i = blockIdx.x * blockDim.x + threadIdx.x;
    if (i == 0) g_ticket = 0;
    if (i < MAXN * 3) g_acc[i] = make_float4(0.f, 0.f, 0.f, 0.f);
}

// ================= kernel 2: edge scatter (vector RED) =====
__global__ void __launch_bounds__(256)
k_edges(const int* __restrict__ row, const float* __restrict__ frames, int E)
{
    __shared__ float buf[8][288];
    const int w = threadIdx.x >> 5, lane = threadIdx.x & 31;
    const long e0 = ((long)blockIdx.x * 8 + w) * 32;
    if (e0 >= E) return;
    const int cnt = (int)min((long)32, (long)E - e0);
    const float* src = frames + e0 * 9;
    for (int i = lane; i < cnt * 9; i += 32) buf[w][i] = src[i];
    int s = (lane < cnt) ? row[e0 + lane] : -1;
    __syncwarp();
    if (s >= 0) {
        const float* f = &buf[w][lane * 9];
        float* dst = (float*)(g_acc + (size_t)s * 3);
        asm volatile("red.global.add.v4.f32 [%0], {%1,%2,%3,%4};"
                     :: "l"(dst), "f"(f[0]), "f"(f[1]), "f"(f[2]), "f"(f[3]) : "memory");
        asm volatile("red.global.add.v4.f32 [%0], {%1,%2,%3,%4};"
                     :: "l"(dst + 4), "f"(f[4]), "f"(f[5]), "f"(f[6]), "f"(f[7]) : "memory");
        asm volatile("red.global.add.v4.f32 [%0], {%1,%2,%3,%4};"
                     :: "l"(dst + 8), "f"(f[8]), "f"(1.0f), "f"(0.0f), "f"(0.0f) : "memory");
    }
}

// ================= kernel 3: fused node kernel =============
__global__ void __launch_bounds__(512, 1)
k_nodes(const float* __restrict__ scalar,
        const float* __restrict__ vector,
        const float* __restrict__ W_down, const float* __restrict__ W_df,
        const float* __restrict__ W_so,   const float* __restrict__ b_so,
        const float* __restrict__ W_up,   const float* __restrict__ W_g,
        const float* __restrict__ b_g,
        float* __restrict__ out1, float* __restrict__ out2, int N)
{
    extern __shared__ float sm[];
    const int tid  = threadIdx.x;
    const int wid  = tid >> 5;
    const int lane = tid & 31;
    const int lane4 = lane << 2;

    // ---- stage weights ----
    for (int i = tid; i < 153 * 128; i += blockDim.x) {
        int o = i / 153, k = i - o * 153;
        sm[OFF_WSO + k * 132 + o] = W_so[i];
    }
    for (int i = tid; i < 128 * 16; i += blockDim.x) {
        int o = i >> 7, k = i & 127;
        sm[OFF_WG + o * 134 + k] = W_g[i];
    }
    for (int i = tid; i < 256; i += blockDim.x) {
        int o = i >> 4, h = i & 15;         // W_up[o][h] -> [h*16+o]
        sm[OFF_WUP + h * 16 + o] = W_up[i];
        int hh = i >> 4, c = i & 15;        // W_down[h][c] -> [c*16+h]
        sm[OFF_WDOWN + c * 16 + hh] = W_down[i];
    }
    for (int i = tid; i < 48; i += blockDim.x) {
        int c = i >> 4, k = i & 15;         // W_df (3,16)
        sm[OFF_WDF + k * 3 + c] = W_df[i];
    }
    for (int i = tid; i < 128; i += blockDim.x) sm[OFF_BSO + i] = b_so[i];
    for (int i = tid; i < 16;  i += blockDim.x) sm[OFF_BG  + i] = b_g[i];
    __syncthreads();

    float* wb   = sm + OFF_WARP + wid * WARP_STRIDE;
    float* mgT  = wb;                 // [k*10 + j]
    float* vecb = wb;                 // aliases mgT rows 0..38 (transient)
    float* vhb  = wb + VH_OFF;        // [j*48 + d*16 + h]

    const int o16 = lane & 15;
    const int h16 = lane >> 4;

    float wu[16];
#pragma unroll
    for (int hh = 0; hh < 16; hh++) wu[hh] = sm[OFF_WUP + hh * 16 + o16];

    const float4 bb  = *(const float4*)&sm[OFF_BSO + lane4];
    const float  bgv = sm[OFF_BG + o16];

    const int nGroups = (N + NPW - 1) / NPW;
    const int totV = N * 48;

    for (;;) {
        int grp = 0;
        if (lane == 0) grp = atomicAdd(&g_ticket, 1);
        grp = __shfl_sync(0xffffffffu, grp, 0);
        if (grp >= nGroups) break;
        const int base = grp * NPW;

        // ---------- prep phase 1: load 8 node vectors into vecb ----------
        {
            const int gb = base * 48;
#pragma unroll
            for (int i = 0; i < 12; i++) {
                int idx = lane + 32 * i;
                vecb[idx] = (gb + idx < totV) ? vector[gb + idx] : 0.0f;
            }
        }
        __syncwarp();

        // ---------- prep phase 2: vh (full warp), sh (lanes<24) ----------
#pragma unroll
        for (int t = 0; t < 4; t++) {
            const int p = lane + 32 * t;
            const int j = p >> 4, h = p & 15;
            float vh0 = 0.f, vh1 = 0.f, vh2 = 0.f;
#pragma unroll
            for (int c = 0; c < 16; c++) {
                float w = sm[OFF_WDOWN + c * 16 + h];
                vh0 = fmaf(w, vecb[j * 48 + c * 3 + 0], vh0);
                vh1 = fmaf(w, vecb[j * 48 + c * 3 + 1], vh1);
                vh2 = fmaf(w, vecb[j * 48 + c * 3 + 2], vh2);
            }
            mgT[(128 + h) * 10 + j] = sqrtf(vh0 * vh0 + vh1 * vh1 + vh2 * vh2 + EPS);
            vhb[j * 48 +      h] = vh0;
            vhb[j * 48 + 16 + h] = vh1;
            vhb[j * 48 + 32 + h] = vh2;
        }
        if (lane < 24) {
            const int j = lane / 3, c = lane - 3 * j;
            const int n = base + j;
            float d0 = 0.f, d1 = 0.f, d2 = 0.f;
#pragma unroll
            for (int k = 0; k < 16; k++) {
                float w = sm[OFF_WDF + k * 3 + c];
                d0 = fmaf(w, vecb[j * 48 + k * 3 + 0], d0);
                d1 = fmaf(w, vecb[j * 48 + k * 3 + 1], d1);
                d2 = fmaf(w, vecb[j * 48 + k * 3 + 2], d2);
            }
            float4 q0, q1, q2;
            if (n < N) {
                q0 = g_acc[(size_t)n * 3 + 0];
                q1 = g_acc[(size_t)n * 3 + 1];
                q2 = g_acc[(size_t)n * 3 + 2];
            } else {
                q0 = q1 = q2 = make_float4(0, 0, 0, 1);
            }
            float inv = __fdividef(1.0f, fmaxf(q2.y, 1.0f));
            mgT[(144 + c * 3 + 0) * 10 + j] = (q0.x * d0 + q0.y * d1 + q0.z * d2) * inv;
            mgT[(144 + c * 3 + 1) * 10 + j] = (q0.w * d0 + q1.x * d1 + q1.y * d2) * inv;
            mgT[(144 + c * 3 + 2) * 10 + j] = (q1.z * d0 + q1.w * d1 + q2.x * d2) * inv;
        }
        __syncwarp();

        // ---------- prep phase 3: scalar features -> mgT rows 0..127 ----------
#pragma unroll
        for (int j = 0; j < NPW; j++) {
            const int n = base + j;
            if (n < N) {
                const float* sp = scalar + (size_t)n * 128;
#pragma unroll
                for (int i = 0; i < 4; i++)
                    mgT[(lane + 32 * i) * 10 + j] = sp[lane + 32 * i];
            } else {
#pragma unroll
                for (int i = 0; i < 4; i++)
                    mgT[(lane + 32 * i) * 10 + j] = 0.0f;
            }
        }
        __syncwarp();

        // ---------- main GEMM: FFMA2, 8 nodes x 4 outputs/lane, K=153 ----------
        ull a0_0 = pk2(bb.x, bb.x), a0_1 = a0_0, a0_2 = a0_0, a0_3 = a0_0;
        ull a1_0 = pk2(bb.y, bb.y), a1_1 = a1_0, a1_2 = a1_0, a1_3 = a1_0;
        ull a2_0 = pk2(bb.z, bb.z), a2_1 = a2_0, a2_2 = a2_0, a2_3 = a2_0;
        ull a3_0 = pk2(bb.w, bb.w), a3_1 = a3_0, a3_2 = a3_0, a3_3 = a3_0;

#pragma unroll 3
        for (int k = 0; k < 153; k++) {
            const float4 w4 = *(const float4*)&sm[OFF_WSO + k * 132 + lane4];
            const ull w0 = pk2(w4.x, w4.x);
            const ull w1 = pk2(w4.y, w4.y);
            const ull w2 = pk2(w4.z, w4.z);
            const ull w3 = pk2(w4.w, w4.w);
            const ull* mrow = (const ull*)(mgT + k * 10);
            const ull m0 = mrow[0], m1 = mrow[1], m2 = mrow[2], m3 = mrow[3];
            a0_0 = ffma2(w0, m0, a0_0); a0_1 = ffma2(w0, m1, a0_1);
            a0_2 = ffma2(w0, m2, a0_2); a0_3 = ffma2(w0, m3, a0_3);
            a1_0 = ffma2(w1, m0, a1_0); a1_1 = ffma2(w1, m1, a1_1);
            a1_2 = ffma2(w1, m2, a1_2); a1_3 = ffma2(w1, m3, a1_3);
            a2_0 = ffma2(w2, m0, a2_0); a2_1 = ffma2(w2, m1, a2_1);
            a2_2 = ffma2(w2, m2, a2_2); a2_3 = ffma2(w2, m3, a2_3);
            a3_0 = ffma2(w3, m0, a3_0); a3_1 = ffma2(w3, m1, a3_1);
            a3_2 = ffma2(w3, m2, a3_2); a3_3 = ffma2(w3, m3, a3_3);
        }
        __syncwarp();

        // ---------- silu + out1 + msil [j*132 + k] ----------
        float sil[4][8];
        {
            ull A[4][4] = {{a0_0,a0_1,a0_2,a0_3},{a1_0,a1_1,a1_2,a1_3},
                           {a2_0,a2_1,a2_2,a2_3},{a3_0,a3_1,a3_2,a3_3}};
#pragma unroll
            for (int i = 0; i < 4; i++)
#pragma unroll
                for (int t = 0; t < 4; t++) {
                    float lo, hi; unpk2(A[i][t], lo, hi);
                    sil[i][2*t]   = __fdividef(lo, 1.0f + __expf(-lo));
                    sil[i][2*t+1] = __fdividef(hi, 1.0f + __expf(-hi));
                }
        }
        float* msil = wb;   // overwrites mgT
#pragma unroll
        for (int j = 0; j < NPW; j++) {
            float4 o4 = make_float4(sil[0][j], sil[1][j], sil[2][j], sil[3][j]);
            *(float4*)&msil[j * 132 + lane4] = o4;
            if (base + j < N)
                *(float4*)(out1 + (size_t)(base + j) * 128 + lane4) = o4;
        }
        __syncwarp();

        // ---------- gate GEMM: even/odd-k packed halves ----------
        // lane (h16,o16) covers output o16 for nodes j = 4*h16 + t
        ull g01[4];
#pragma unroll
        for (int t = 0; t < 4; t++) g01[t] = 0ull;
#pragma unroll 8
        for (int kp = 0; kp < 64; kp++) {
            const int k = kp * 2;
            const ull wgp = *(const ull*)&sm[OFF_WG + o16 * 134 + k];
#pragma unroll
            for (int t = 0; t < 4; t++) {
                const int j = 4 * h16 + t;
                const ull mp = *(const ull*)&msil[j * 132 + k];
                g01[t] = ffma2(wgp, mp, g01[t]);
            }
        }
        float gv[4];
#pragma unroll
        for (int t = 0; t < 4; t++) {
            float lo, hi; unpk2(g01[t], lo, hi);
            gv[t] = lo + hi + bgv;
        }

        // ---------- vrep ----------
#pragma unroll
        for (int t = 0; t < 4; t++) {
            const int j = 4 * h16 + t;
            const int n = base + j;
            const float sg = __fdividef(1.0f, 1.0f + __expf(-gv[t]));
            const float* vh = vhb + j * 48;
            float r0 = 0.f, r1 = 0.f, r2 = 0.f;
#pragma unroll
            for (int hh = 0; hh < 16; hh++) {
                r0 = fmaf(wu[hh], vh[hh],      r0);
                r1 = fmaf(wu[hh], vh[16 + hh], r1);
                r2 = fmaf(wu[hh], vh[32 + hh], r2);
            }
            if (n < N) {
                float* od = out2 + (size_t)n * 48 + o16 * 3;
                od[0] = r0 * sg; od[1] = r1 * sg; od[2] = r2 * sg;
            }
        }
        __syncwarp();
    }
}

// ================= launch =================
extern "C" void kernel_launch(void* const* d_in, const int* in_sizes, int n_in,
                              void* d_out, int out_size)
{
    const float* scalar  = (const float*)d_in[0];
    const float* vector  = (const float*)d_in[1];
    const int*   eidx    = (const int*)  d_in[2];
    const float* frames  = (const float*)d_in[3];
    const float* W_down  = (const float*)d_in[4];
    const float* W_df    = (const float*)d_in[5];
    const float* W_so    = (const float*)d_in[6];
    const float* b_so    = (const float*)d_in[7];
    const float* W_up    = (const float*)d_in[8];
    const float* W_g     = (const float*)d_in[9];
    const float* b_g     = (const float*)d_in[10];

    const int N = in_sizes[0] / 128;
    const int E = in_sizes[2] / 2;
    const int* row = eidx;

    float* out1 = (float*)d_out;
    float* out2 = out1 + (size_t)N * 128;

    cudaFuncSetAttribute(k_nodes, cudaFuncAttributeMaxDynamicSharedMemorySize,
                         SMEM_BYTES);

    k_zero<<<(MAXN * 3 + 255) / 256, 256>>>();
    k_edges<<<(E + 255) / 256, 256>>>(row, frames, E);
    k_nodes<<<148, 512, SMEM_BYTES>>>(scalar, vector, W_down, W_df, W_so, b_so,
                                      W_up, W_g, b_g, out1, out2, N);
}